// round 6
// baseline (speedup 1.0000x reference)
#include <cuda_runtime.h>
#include <cuda_bf16.h>
#include <cstdint>

#define N_NODES 50000
#define E_EDGES 625000
#define HIDDEN  128

// ---------------- scratch ----------------------------------------------------
__device__ float g_sum[N_NODES * HIDDEN];
__device__ int   g_count[N_NODES];
__device__ int   g_offset[N_NODES];
__device__ int   g_cursor[N_NODES];
__device__ int   g_edge_ids[E_EDGES];

// ---------------- prologue ----------------------------------------------------
__global__ void hist4_kernel(const int4* __restrict__ er4) {
    int t = blockIdx.x * blockDim.x + threadIdx.x;
    if (t < E_EDGES / 4) {
        int4 r = er4[t];
        atomicAdd(&g_count[r.x], 1);
        atomicAdd(&g_count[r.y], 1);
        atomicAdd(&g_count[r.z], 1);
        atomicAdd(&g_count[r.w], 1);
    }
}
__global__ void scan_kernel() {
    __shared__ int s[1024];
    const int t = threadIdx.x;
    const int CHUNK = (N_NODES + 1023) / 1024;
    int base = t * CHUNK;
    int sum = 0;
    for (int i = 0; i < CHUNK; i++) {
        int idx = base + i;
        if (idx < N_NODES) sum += g_count[idx];
    }
    s[t] = sum;
    __syncthreads();
    for (int off = 1; off < 1024; off <<= 1) {
        int v = 0;
        if (t >= off) v = s[t - off];
        __syncthreads();
        if (t >= off) s[t] += v;
        __syncthreads();
    }
    int run = (t == 0) ? 0 : s[t - 1];
    for (int i = 0; i < CHUNK; i++) {
        int idx = base + i;
        if (idx < N_NODES) {
            g_offset[idx] = run;
            g_cursor[idx] = run;
            run += g_count[idx];
        }
    }
}
__global__ void fill4_kernel(const int4* __restrict__ er4) {
    int t = blockIdx.x * blockDim.x + threadIdx.x;
    if (t < E_EDGES / 4) {
        int4 r = er4[t];
        int base = t * 4;
        int p0 = atomicAdd(&g_cursor[r.x], 1); g_edge_ids[p0] = base + 0;
        int p1 = atomicAdd(&g_cursor[r.y], 1); g_edge_ids[p1] = base + 1;
        int p2 = atomicAdd(&g_cursor[r.z], 1); g_edge_ids[p2] = base + 2;
        int p3 = atomicAdd(&g_cursor[r.w], 1); g_edge_ids[p3] = base + 3;
    }
}
__global__ void gather_kernel(const float* __restrict__ edge_attr) {
    int gtid = blockIdx.x * blockDim.x + threadIdx.x;
    int warp = gtid >> 5;
    int lane = gtid & 31;
    if (warp >= N_NODES) return;
    int start = g_offset[warp];
    int cnt   = g_count[warp];
    float4 acc = make_float4(0.f, 0.f, 0.f, 0.f);
    const float4* ea4 = (const float4*)edge_attr;
    int i = 0;
    for (; i + 8 <= cnt; i += 8) {
        int e[8];
        #pragma unroll
        for (int u = 0; u < 8; u++) e[u] = g_edge_ids[start + i + u];
        float4 v[8];
        #pragma unroll
        for (int u = 0; u < 8; u++) v[u] = ea4[(size_t)e[u] * 32 + lane];
        #pragma unroll
        for (int u = 0; u < 8; u++) {
            acc.x += v[u].x; acc.y += v[u].y; acc.z += v[u].z; acc.w += v[u].w;
        }
    }
    for (; i < cnt; i++) {
        int e = g_edge_ids[start + i];
        float4 v = ea4[(size_t)e * 32 + lane];
        acc.x += v.x; acc.y += v.y; acc.z += v.z; acc.w += v.w;
    }
    ((float4*)g_sum)[(size_t)warp * 32 + lane] = acc;
}

// ---------------- MLP via mma.sync, 2 row-frags, LDS.128 fragments ----------
__device__ __forceinline__ void mma_bf16(float4& d,
    uint32_t a0, uint32_t a1, uint32_t a2, uint32_t a3,
    uint32_t b0, uint32_t b1) {
    asm volatile(
        "mma.sync.aligned.m16n8k16.row.col.f32.bf16.bf16.f32 "
        "{%0,%1,%2,%3}, {%4,%5,%6,%7}, {%8,%9}, {%0,%1,%2,%3};"
        : "+f"(d.x), "+f"(d.y), "+f"(d.z), "+f"(d.w)
        : "r"(a0), "r"(a1), "r"(a2), "r"(a3), "r"(b0), "r"(b1));
}
__device__ __forceinline__ void split2(float a, float b, uint32_t& hi, uint32_t& lo) {
    __nv_bfloat16 ha = __float2bfloat16_rn(a);
    __nv_bfloat16 hb = __float2bfloat16_rn(b);
    __nv_bfloat162 H; H.x = ha; H.y = hb;
    hi = *(uint32_t*)&H;
    __nv_bfloat162 L;
    L.x = __float2bfloat16_rn(a - __bfloat162float(ha));
    L.y = __float2bfloat16_rn(b - __bfloat162float(hb));
    lo = *(uint32_t*)&L;
}

#define TILE_M  256
#define N_TILES ((N_NODES + TILE_M - 1) / TILE_M)   // 196
// interleaved weight tiles: per j row, 16B chunks {b0h,b1h,b0l,b1l}
// W1: stride 68 (16B units, 64 used + 4 pad, 68 % 8 == 4 -> conflict-free LDS.128)
// W2: stride 36 (32 used + 4 pad)
#define W1_BYTES (128 * 68 * 16)   // 139264
#define W2_BYTES (128 * 36 * 16)   // 73728
#define MLP_SMEM (W1_BYTES + W2_BYTES + 256 * 4)   // 214016

__global__ __launch_bounds__(256, 1)
void mlp_mma_kernel(const float* __restrict__ x,
                    const float* __restrict__ W1, const float* __restrict__ b1,
                    const float* __restrict__ W2, const float* __restrict__ b2,
                    float* __restrict__ out) {
    extern __shared__ char smem[];
    char*  W1i = smem;
    char*  W2i = smem + W1_BYTES;
    float* b1s = (float*)(smem + W1_BYTES + W2_BYTES);
    float* b2s = b1s + 128;

    const int tid = threadIdx.x;

    // ---- stage W1/W2 interleaved + split (gmem coalesced, smem STS.16) ----
    for (int i = tid; i < 256 * 128; i += 256) {
        int k = i >> 7, j = i & 127;
        float v = W1[i];
        __nv_bfloat16 h = __float2bfloat16_rn(v);
        __nv_bfloat16 l = __float2bfloat16_rn(v - __bfloat162float(h));
        int ks = k >> 4, m = k & 15;
        int q = (m & 7) >> 1, s = m & 1, t = m >> 3;
        char* p8 = W1i + ((j * 68 + ks * 4 + q) << 4) + t * 4 + s * 2;
        *(__nv_bfloat16*)p8 = h;
        *(__nv_bfloat16*)(p8 + 8) = l;
    }
    for (int i = tid; i < 128 * 128; i += 256) {
        int k = i >> 7, j = i & 127;
        float v = W2[i];
        __nv_bfloat16 h = __float2bfloat16_rn(v);
        __nv_bfloat16 l = __float2bfloat16_rn(v - __bfloat162float(h));
        int ks = k >> 4, m = k & 15;
        int q = (m & 7) >> 1, s = m & 1, t = m >> 3;
        char* p8 = W2i + ((j * 36 + ks * 4 + q) << 4) + t * 4 + s * 2;
        *(__nv_bfloat16*)p8 = h;
        *(__nv_bfloat16*)(p8 + 8) = l;
    }
    if (tid < 128) { b1s[tid] = b1[tid]; b2s[tid] = b2[tid]; }
    __syncthreads();
    // no syncs in the tile loop: warps fully independent

    const int w    = tid >> 5;
    const int lane = tid & 31;
    const int p    = lane >> 2;
    const int q    = lane & 3;
    const char* B1p = W1i + ((p * 68 + q) << 4);
    const char* B2p = W2i + ((p * 36 + q) << 4);

    for (int tile = blockIdx.x; tile < N_TILES; tile += gridDim.x) {
        const int rb = tile * TILE_M + w * 32 + p;
        const int r0 = rb, r1 = rb + 8, r2 = rb + 16, r3 = rb + 24;
        const bool o0 = r0 < N_NODES, o1 = r1 < N_NODES,
                   o2 = r2 < N_NODES, o3 = r3 < N_NODES;
        const float* x0 = x + (size_t)r0 * 128;
        const float* x1 = x + (size_t)r1 * 128;
        const float* x2 = x + (size_t)r2 * 128;
        const float* x3 = x + (size_t)r3 * 128;
        const float* s0 = g_sum + (size_t)r0 * 128;
        const float* s1 = g_sum + (size_t)r1 * 128;
        const float* s2 = g_sum + (size_t)r2 * 128;
        const float* s3 = g_sum + (size_t)r3 * 128;

        float4 acc0[16], acc1[16];
        #pragma unroll
        for (int nf = 0; nf < 16; nf++) {
            acc0[nf] = make_float4(0.f, 0.f, 0.f, 0.f);
            acc1[nf] = make_float4(0.f, 0.f, 0.f, 0.f);
        }

        // ---- layer 1 ----
        #pragma unroll
        for (int ks = 0; ks < 16; ks++) {
            const int ko = (ks & 7) * 16 + q * 2;
            const float* P0 = (ks < 8) ? x0 : s0;
            const float* P1 = (ks < 8) ? x1 : s1;
            const float* P2 = (ks < 8) ? x2 : s2;
            const float* P3 = (ks < 8) ? x3 : s3;
            float2 z = make_float2(0.f, 0.f);
            float2 v0a = o0 ? *(const float2*)(P0 + ko)     : z;
            float2 v0b = o0 ? *(const float2*)(P0 + ko + 8) : z;
            float2 v1a = o1 ? *(const float2*)(P1 + ko)     : z;
            float2 v1b = o1 ? *(const float2*)(P1 + ko + 8) : z;
            float2 v2a = o2 ? *(const float2*)(P2 + ko)     : z;
            float2 v2b = o2 ? *(const float2*)(P2 + ko + 8) : z;
            float2 v3a = o3 ? *(const float2*)(P3 + ko)     : z;
            float2 v3b = o3 ? *(const float2*)(P3 + ko + 8) : z;
            uint32_t a0h, a0l, a1h, a1l, a2h, a2l, a3h, a3l;
            uint32_t c0h, c0l, c1h, c1l, c2h, c2l, c3h, c3l;
            split2(v0a.x, v0a.y, a0h, a0l);
            split2(v1a.x, v1a.y, a1h, a1l);
            split2(v0b.x, v0b.y, a2h, a2l);
            split2(v1b.x, v1b.y, a3h, a3l);
            split2(v2a.x, v2a.y, c0h, c0l);
            split2(v3a.x, v3a.y, c1h, c1l);
            split2(v2b.x, v2b.y, c2h, c2l);
            split2(v3b.x, v3b.y, c3h, c3l);
            const char* wp = B1p + ks * 64;
            #pragma unroll
            for (int nf = 0; nf < 16; nf++) {
                uint4 bw = *(const uint4*)(wp + nf * 8704);   // 8*68*16
                mma_bf16(acc0[nf], a0h, a1h, a2h, a3h, bw.x, bw.y);
                mma_bf16(acc0[nf], a0h, a1h, a2h, a3h, bw.z, bw.w);
                mma_bf16(acc0[nf], a0l, a1l, a2l, a3l, bw.x, bw.y);
                mma_bf16(acc1[nf], c0h, c1h, c2h, c3h, bw.x, bw.y);
                mma_bf16(acc1[nf], c0h, c1h, c2h, c3h, bw.z, bw.w);
                mma_bf16(acc1[nf], c0l, c1l, c2l, c3l, bw.x, bw.y);
            }
        }

        // ---- bias + relu + split -> layer-2 A frags ----
        uint32_t ah0[8][4], al0[8][4], ah1[8][4], al1[8][4];
        #pragma unroll
        for (int ks2 = 0; ks2 < 8; ks2++) {
            #pragma unroll
            for (int half = 0; half < 2; half++) {
                const int nf = ks2 * 2 + half;
                float2 bv = *(const float2*)&b1s[nf * 8 + q * 2];
                float hx = fmaxf(acc0[nf].x + bv.x, 0.f);
                float hy = fmaxf(acc0[nf].y + bv.y, 0.f);
                float hz = fmaxf(acc0[nf].z + bv.x, 0.f);
                float hw = fmaxf(acc0[nf].w + bv.y, 0.f);
                split2(hx, hy, ah0[ks2][half * 2 + 0], al0[ks2][half * 2 + 0]);
                split2(hz, hw, ah0[ks2][half * 2 + 1], al0[ks2][half * 2 + 1]);
                hx = fmaxf(acc1[nf].x + bv.x, 0.f);
                hy = fmaxf(acc1[nf].y + bv.y, 0.f);
                hz = fmaxf(acc1[nf].z + bv.x, 0.f);
                hw = fmaxf(acc1[nf].w + bv.y, 0.f);
                split2(hx, hy, ah1[ks2][half * 2 + 0], al1[ks2][half * 2 + 0]);
                split2(hz, hw, ah1[ks2][half * 2 + 1], al1[ks2][half * 2 + 1]);
            }
        }

        // ---- layer 2, two j-halves to bound register pressure ----
        #pragma unroll
        for (int jh = 0; jh < 2; jh++) {
            float4 d0[8], d1[8];
            #pragma unroll
            for (int nf = 0; nf < 8; nf++) {
                d0[nf] = make_float4(0.f, 0.f, 0.f, 0.f);
                d1[nf] = make_float4(0.f, 0.f, 0.f, 0.f);
            }
            #pragma unroll
            for (int ks2 = 0; ks2 < 8; ks2++) {
                const char* wp = B2p + ks2 * 64 + jh * 8 * 4608;   // 8*36*16
                #pragma unroll
                for (int nf = 0; nf < 8; nf++) {
                    uint4 bw = *(const uint4*)(wp + nf * 4608);
                    mma_bf16(d0[nf], ah0[ks2][0], ah0[ks2][1], ah0[ks2][2], ah0[ks2][3], bw.x, bw.y);
                    mma_bf16(d0[nf], ah0[ks2][0], ah0[ks2][1], ah0[ks2][2], ah0[ks2][3], bw.z, bw.w);
                    mma_bf16(d0[nf], al0[ks2][0], al0[ks2][1], al0[ks2][2], al0[ks2][3], bw.x, bw.y);
                    mma_bf16(d1[nf], ah1[ks2][0], ah1[ks2][1], ah1[ks2][2], ah1[ks2][3], bw.x, bw.y);
                    mma_bf16(d1[nf], ah1[ks2][0], ah1[ks2][1], ah1[ks2][2], ah1[ks2][3], bw.z, bw.w);
                    mma_bf16(d1[nf], al1[ks2][0], al1[ks2][1], al1[ks2][2], al1[ks2][3], bw.x, bw.y);
                }
            }
            // epilogue: + b2 + residual, store
            #pragma unroll
            for (int nf = 0; nf < 8; nf++) {
                const int j = jh * 64 + nf * 8 + q * 2;
                float2 bv = *(const float2*)&b2s[j];
                if (o0) {
                    float2 xr = *(const float2*)(x0 + j);
                    float2 o = make_float2(d0[nf].x + bv.x + xr.x, d0[nf].y + bv.y + xr.y);
                    *(float2*)(out + (size_t)r0 * 128 + j) = o;
                }
                if (o1) {
                    float2 xr = *(const float2*)(x1 + j);
                    float2 o = make_float2(d0[nf].z + bv.x + xr.x, d0[nf].w + bv.y + xr.y);
                    *(float2*)(out + (size_t)r1 * 128 + j) = o;
                }
                if (o2) {
                    float2 xr = *(const float2*)(x2 + j);
                    float2 o = make_float2(d1[nf].x + bv.x + xr.x, d1[nf].y + bv.y + xr.y);
                    *(float2*)(out + (size_t)r2 * 128 + j) = o;
                }
                if (o3) {
                    float2 xr = *(const float2*)(x3 + j);
                    float2 o = make_float2(d1[nf].z + bv.x + xr.x, d1[nf].w + bv.y + xr.y);
                    *(float2*)(out + (size_t)r3 * 128 + j) = o;
                }
            }
        }
    }
}

// ---------------- launcher ---------------------------------------------------
extern "C" void kernel_launch(void* const* d_in, const int* in_sizes, int n_in,
                              void* d_out, int out_size) {
    const float* x          = (const float*)d_in[0];
    const int*   edge_row   = (const int*)d_in[1];   // int64 downcast; first E = row
    const float* edge_attr  = (const float*)d_in[2];
    const float* W1         = (const float*)d_in[5];
    const float* b1         = (const float*)d_in[6];
    const float* W2         = (const float*)d_in[7];
    const float* b2         = (const float*)d_in[8];
    float*       out        = (float*)d_out;

    void* gcnt = nullptr;
    cudaGetSymbolAddress(&gcnt, g_count);
    cudaMemsetAsync(gcnt, 0, N_NODES * sizeof(int));

    hist4_kernel<<<(E_EDGES / 4 + 255) / 256, 256>>>((const int4*)edge_row);
    scan_kernel<<<1, 1024>>>();
    fill4_kernel<<<(E_EDGES / 4 + 255) / 256, 256>>>((const int4*)edge_row);
    gather_kernel<<<(N_NODES * 32 + 255) / 256, 256>>>(edge_attr);

    cudaFuncSetAttribute(mlp_mma_kernel, cudaFuncAttributeMaxDynamicSharedMemorySize, MLP_SMEM);
    mlp_mma_kernel<<<148, 256, MLP_SMEM>>>(x, W1, b1, W2, b2, out);
}

// round 7
// speedup vs baseline: 1.0732x; 1.0732x over previous
#include <cuda_runtime.h>
#include <cuda_bf16.h>
#include <cstdint>

#define N_NODES 50000
#define E_EDGES 625000
#define HIDDEN  128

// ---------------- scratch ----------------------------------------------------
__device__ float g_sum[N_NODES * HIDDEN];
__device__ int   g_count[N_NODES];
__device__ int   g_offset[N_NODES];
__device__ int   g_cursor[N_NODES];
__device__ int   g_edge_ids[E_EDGES];

// ---------------- prologue ----------------------------------------------------
__global__ void hist4_kernel(const int4* __restrict__ er4) {
    int t = blockIdx.x * blockDim.x + threadIdx.x;
    if (t < E_EDGES / 4) {
        int4 r = er4[t];
        atomicAdd(&g_count[r.x], 1);
        atomicAdd(&g_count[r.y], 1);
        atomicAdd(&g_count[r.z], 1);
        atomicAdd(&g_count[r.w], 1);
    }
}
__global__ void scan_kernel() {
    __shared__ int s[1024];
    const int t = threadIdx.x;
    const int CHUNK = (N_NODES + 1023) / 1024;
    int base = t * CHUNK;
    int sum = 0;
    for (int i = 0; i < CHUNK; i++) {
        int idx = base + i;
        if (idx < N_NODES) sum += g_count[idx];
    }
    s[t] = sum;
    __syncthreads();
    for (int off = 1; off < 1024; off <<= 1) {
        int v = 0;
        if (t >= off) v = s[t - off];
        __syncthreads();
        if (t >= off) s[t] += v;
        __syncthreads();
    }
    int run = (t == 0) ? 0 : s[t - 1];
    for (int i = 0; i < CHUNK; i++) {
        int idx = base + i;
        if (idx < N_NODES) {
            g_offset[idx] = run;
            g_cursor[idx] = run;
            run += g_count[idx];
        }
    }
}
__global__ void fill4_kernel(const int4* __restrict__ er4) {
    int t = blockIdx.x * blockDim.x + threadIdx.x;
    if (t < E_EDGES / 4) {
        int4 r = er4[t];
        int base = t * 4;
        int p0 = atomicAdd(&g_cursor[r.x], 1); g_edge_ids[p0] = base + 0;
        int p1 = atomicAdd(&g_cursor[r.y], 1); g_edge_ids[p1] = base + 1;
        int p2 = atomicAdd(&g_cursor[r.z], 1); g_edge_ids[p2] = base + 2;
        int p3 = atomicAdd(&g_cursor[r.w], 1); g_edge_ids[p3] = base + 3;
    }
}
__global__ void gather_kernel(const float* __restrict__ edge_attr) {
    int gtid = blockIdx.x * blockDim.x + threadIdx.x;
    int warp = gtid >> 5;
    int lane = gtid & 31;
    if (warp >= N_NODES) return;
    int start = g_offset[warp];
    int cnt   = g_count[warp];
    float4 acc = make_float4(0.f, 0.f, 0.f, 0.f);
    const float4* ea4 = (const float4*)edge_attr;
    int i = 0;
    for (; i + 8 <= cnt; i += 8) {
        int e[8];
        #pragma unroll
        for (int u = 0; u < 8; u++) e[u] = g_edge_ids[start + i + u];
        float4 v[8];
        #pragma unroll
        for (int u = 0; u < 8; u++) v[u] = ea4[(size_t)e[u] * 32 + lane];
        #pragma unroll
        for (int u = 0; u < 8; u++) {
            acc.x += v[u].x; acc.y += v[u].y; acc.z += v[u].z; acc.w += v[u].w;
        }
    }
    for (; i < cnt; i++) {
        int e = g_edge_ids[start + i];
        float4 v = ea4[(size_t)e * 32 + lane];
        acc.x += v.x; acc.y += v.y; acc.z += v.z; acc.w += v.w;
    }
    ((float4*)g_sum)[(size_t)warp * 32 + lane] = acc;
}

// ---------------- MLP via mma.sync: TILE_M=128, interleaved LDS.128 weights --
__device__ __forceinline__ void mma_bf16(float4& d,
    uint32_t a0, uint32_t a1, uint32_t a2, uint32_t a3,
    uint32_t b0, uint32_t b1) {
    asm volatile(
        "mma.sync.aligned.m16n8k16.row.col.f32.bf16.bf16.f32 "
        "{%0,%1,%2,%3}, {%4,%5,%6,%7}, {%8,%9}, {%0,%1,%2,%3};"
        : "+f"(d.x), "+f"(d.y), "+f"(d.z), "+f"(d.w)
        : "r"(a0), "r"(a1), "r"(a2), "r"(a3), "r"(b0), "r"(b1));
}
__device__ __forceinline__ void split2(float a, float b, uint32_t& hi, uint32_t& lo) {
    __nv_bfloat16 ha = __float2bfloat16_rn(a);
    __nv_bfloat16 hb = __float2bfloat16_rn(b);
    __nv_bfloat162 H; H.x = ha; H.y = hb;
    hi = *(uint32_t*)&H;
    __nv_bfloat162 L;
    L.x = __float2bfloat16_rn(a - __bfloat162float(ha));
    L.y = __float2bfloat16_rn(b - __bfloat162float(hb));
    lo = *(uint32_t*)&L;
}

#define TILE_M  128
#define N_TILES ((N_NODES + TILE_M - 1) / TILE_M)   // 391
// interleaved weights: 16B chunk {b0h,b1h,b0l,b1l} at chunk index j*STR + ks*4 + q
// strides in 16B units: W1 68 (64+4 pad), W2 36 (32+4 pad); % 8 == 4 -> conflict-free
#define W1_BYTES (128 * 68 * 16)   // 139264
#define W2_BYTES (128 * 36 * 16)   // 73728
#define MLP_SMEM (W1_BYTES + W2_BYTES + 256 * 4)   // 214016

__global__ __launch_bounds__(256, 1)
void mlp_mma_kernel(const float* __restrict__ x,
                    const float* __restrict__ W1, const float* __restrict__ b1,
                    const float* __restrict__ W2, const float* __restrict__ b2,
                    float* __restrict__ out) {
    extern __shared__ char smem[];
    char*  W1i = smem;
    char*  W2i = smem + W1_BYTES;
    float* b1s = (float*)(smem + W1_BYTES + W2_BYTES);
    float* b2s = b1s + 128;

    const int tid = threadIdx.x;

    // ---- stage W1/W2 interleaved + split ----
    for (int i = tid; i < 256 * 128; i += 256) {
        int k = i >> 7, j = i & 127;
        float v = W1[i];
        __nv_bfloat16 h = __float2bfloat16_rn(v);
        __nv_bfloat16 l = __float2bfloat16_rn(v - __bfloat162float(h));
        int ks = k >> 4, m = k & 15;
        int q = (m & 7) >> 1, s = m & 1, t = m >> 3;
        char* p8 = W1i + ((j * 68 + ks * 4 + q) << 4) + t * 4 + s * 2;
        *(__nv_bfloat16*)p8 = h;
        *(__nv_bfloat16*)(p8 + 8) = l;
    }
    for (int i = tid; i < 128 * 128; i += 256) {
        int k = i >> 7, j = i & 127;
        float v = W2[i];
        __nv_bfloat16 h = __float2bfloat16_rn(v);
        __nv_bfloat16 l = __float2bfloat16_rn(v - __bfloat162float(h));
        int ks = k >> 4, m = k & 15;
        int q = (m & 7) >> 1, s = m & 1, t = m >> 3;
        char* p8 = W2i + ((j * 36 + ks * 4 + q) << 4) + t * 4 + s * 2;
        *(__nv_bfloat16*)p8 = h;
        *(__nv_bfloat16*)(p8 + 8) = l;
    }
    if (tid < 128) { b1s[tid] = b1[tid]; b2s[tid] = b2[tid]; }
    __syncthreads();
    // no syncs in the tile loop: warps fully independent

    const int w    = tid >> 5;
    const int lane = tid & 31;
    const int p    = lane >> 2;
    const int q    = lane & 3;
    const char* B1p = W1i + ((p * 68 + q) << 4);
    const char* B2p = W2i + ((p * 36 + q) << 4);

    for (int tile = blockIdx.x; tile < N_TILES; tile += gridDim.x) {
        const int row0 = tile * TILE_M + w * 16 + p;
        const int row1 = row0 + 8;
        const bool ok0 = row0 < N_NODES;
        const bool ok1 = row1 < N_NODES;
        const float* xr0 = x + (size_t)row0 * 128;
        const float* xr1 = x + (size_t)row1 * 128;
        const float* sr0 = g_sum + (size_t)row0 * 128;
        const float* sr1 = g_sum + (size_t)row1 * 128;

        // ---- layer 1: 16 K-steps x 16 n-frags ----
        float4 acc[16];
        #pragma unroll
        for (int nf = 0; nf < 16; nf++) acc[nf] = make_float4(0.f, 0.f, 0.f, 0.f);

        #pragma unroll
        for (int ks = 0; ks < 16; ks++) {
            const float* p0 = (ks < 8) ? xr0 : sr0;
            const float* p1 = (ks < 8) ? xr1 : sr1;
            const int ko = (ks & 7) * 16 + q * 2;
            float2 z = make_float2(0.f, 0.f);
            float2 v00 = ok0 ? *(const float2*)(p0 + ko)     : z;
            float2 v01 = ok0 ? *(const float2*)(p0 + ko + 8) : z;
            float2 v10 = ok1 ? *(const float2*)(p1 + ko)     : z;
            float2 v11 = ok1 ? *(const float2*)(p1 + ko + 8) : z;
            uint32_t a0h, a0l, a1h, a1l, a2h, a2l, a3h, a3l;
            split2(v00.x, v00.y, a0h, a0l);
            split2(v10.x, v10.y, a1h, a1l);
            split2(v01.x, v01.y, a2h, a2l);
            split2(v11.x, v11.y, a3h, a3l);
            const char* wp = B1p + ks * 64;
            #pragma unroll
            for (int nf = 0; nf < 16; nf++) {
                uint4 bw = *(const uint4*)(wp + nf * 8704);   // 8*68*16
                mma_bf16(acc[nf], a0h, a1h, a2h, a3h, bw.x, bw.y);
                mma_bf16(acc[nf], a0h, a1h, a2h, a3h, bw.z, bw.w);
                mma_bf16(acc[nf], a0l, a1l, a2l, a3l, bw.x, bw.y);
            }
        }

        // ---- bias + relu + split -> layer-2 A frags (in-register) ----
        uint32_t ah[8][4], al[8][4];
        #pragma unroll
        for (int ks2 = 0; ks2 < 8; ks2++) {
            #pragma unroll
            for (int half = 0; half < 2; half++) {
                const int nf = ks2 * 2 + half;
                float2 bv = *(const float2*)&b1s[nf * 8 + q * 2];
                float hx = fmaxf(acc[nf].x + bv.x, 0.f);
                float hy = fmaxf(acc[nf].y + bv.y, 0.f);
                float hz = fmaxf(acc[nf].z + bv.x, 0.f);
                float hw = fmaxf(acc[nf].w + bv.y, 0.f);
                split2(hx, hy, ah[ks2][half * 2 + 0], al[ks2][half * 2 + 0]);
                split2(hz, hw, ah[ks2][half * 2 + 1], al[ks2][half * 2 + 1]);
            }
        }

        // ---- layer 2: 8 K-steps x 16 n-frags ----
        float4 acc2[16];
        #pragma unroll
        for (int nf = 0; nf < 16; nf++) acc2[nf] = make_float4(0.f, 0.f, 0.f, 0.f);

        #pragma unroll
        for (int ks2 = 0; ks2 < 8; ks2++) {
            const char* wp = B2p + ks2 * 64;
            #pragma unroll
            for (int nf = 0; nf < 16; nf++) {
                uint4 bw = *(const uint4*)(wp + nf * 4608);   // 8*36*16
                mma_bf16(acc2[nf], ah[ks2][0], ah[ks2][1], ah[ks2][2], ah[ks2][3], bw.x, bw.y);
                mma_bf16(acc2[nf], ah[ks2][0], ah[ks2][1], ah[ks2][2], ah[ks2][3], bw.z, bw.w);
                mma_bf16(acc2[nf], al[ks2][0], al[ks2][1], al[ks2][2], al[ks2][3], bw.x, bw.y);
            }
        }

        // ---- epilogue: + b2 + residual, store ----
        #pragma unroll
        for (int nf = 0; nf < 16; nf++) {
            const int j = nf * 8 + q * 2;
            float2 bv = *(const float2*)&b2s[j];
            if (ok0) {
                float2 xr = *(const float2*)(xr0 + j);
                float2 o = make_float2(acc2[nf].x + bv.x + xr.x,
                                       acc2[nf].y + bv.y + xr.y);
                *(float2*)(out + (size_t)row0 * 128 + j) = o;
            }
            if (ok1) {
                float2 xr = *(const float2*)(xr1 + j);
                float2 o = make_float2(acc2[nf].z + bv.x + xr.x,
                                       acc2[nf].w + bv.y + xr.y);
                *(float2*)(out + (size_t)row1 * 128 + j) = o;
            }
        }
    }
}

// ---------------- launcher ---------------------------------------------------
extern "C" void kernel_launch(void* const* d_in, const int* in_sizes, int n_in,
                              void* d_out, int out_size) {
    const float* x          = (const float*)d_in[0];
    const int*   edge_row   = (const int*)d_in[1];   // int64 downcast; first E = row
    const float* edge_attr  = (const float*)d_in[2];
    const float* W1         = (const float*)d_in[5];
    const float* b1         = (const float*)d_in[6];
    const float* W2         = (const float*)d_in[7];
    const float* b2         = (const float*)d_in[8];
    float*       out        = (float*)d_out;

    void* gcnt = nullptr;
    cudaGetSymbolAddress(&gcnt, g_count);
    cudaMemsetAsync(gcnt, 0, N_NODES * sizeof(int));

    hist4_kernel<<<(E_EDGES / 4 + 255) / 256, 256>>>((const int4*)edge_row);
    scan_kernel<<<1, 1024>>>();
    fill4_kernel<<<(E_EDGES / 4 + 255) / 256, 256>>>((const int4*)edge_row);
    gather_kernel<<<(N_NODES * 32 + 255) / 256, 256>>>(edge_attr);

    cudaFuncSetAttribute(mlp_mma_kernel, cudaFuncAttributeMaxDynamicSharedMemorySize, MLP_SMEM);
    mlp_mma_kernel<<<148, 256, MLP_SMEM>>>(x, W1, b1, W2, b2, out);
}

// round 8
// speedup vs baseline: 1.0839x; 1.0100x over previous
#include <cuda_runtime.h>
#include <cuda_bf16.h>
#include <cstdint>

#define N_NODES 50000
#define E_EDGES 625000
#define HIDDEN  128

// ---------------- scratch ----------------------------------------------------
__device__ float g_sum[N_NODES * HIDDEN];
__device__ int   g_count[N_NODES];
__device__ int   g_offset[N_NODES];
__device__ int   g_cursor[N_NODES];
__device__ int   g_edge_ids[E_EDGES];
__device__ int   g_bar;          // device barrier counter (memset to 0 per launch)

// ---------------- 1. histogram ------------------------------------------------
__global__ void hist4_kernel(const int4* __restrict__ er4) {
    int t = blockIdx.x * blockDim.x + threadIdx.x;
    if (t < E_EDGES / 4) {
        int4 r = er4[t];
        atomicAdd(&g_count[r.x], 1);
        atomicAdd(&g_count[r.y], 1);
        atomicAdd(&g_count[r.z], 1);
        atomicAdd(&g_count[r.w], 1);
    }
}

// ---------------- 2. exclusive scan -------------------------------------------
__global__ void scan_kernel() {
    __shared__ int s[1024];
    const int t = threadIdx.x;
    const int CHUNK = (N_NODES + 1023) / 1024;
    int base = t * CHUNK;
    int sum = 0;
    for (int i = 0; i < CHUNK; i++) {
        int idx = base + i;
        if (idx < N_NODES) sum += g_count[idx];
    }
    s[t] = sum;
    __syncthreads();
    for (int off = 1; off < 1024; off <<= 1) {
        int v = 0;
        if (t >= off) v = s[t - off];
        __syncthreads();
        if (t >= off) s[t] += v;
        __syncthreads();
    }
    int run = (t == 0) ? 0 : s[t - 1];
    for (int i = 0; i < CHUNK; i++) {
        int idx = base + i;
        if (idx < N_NODES) {
            g_offset[idx] = run;
            g_cursor[idx] = run;
            run += g_count[idx];
        }
    }
}

// ---------------- 3. fused CSR-fill + gather (device barrier between) --------
#define FG_CTAS 592   // 4 per SM, co-resident -> barrier is safe

__global__ __launch_bounds__(256, 4)
void fillgather_kernel(const int4* __restrict__ er4,
                       const float* __restrict__ edge_attr) {
    const int nthr = gridDim.x * blockDim.x;

    // ---- phase A: CSR fill ----
    for (int t = blockIdx.x * blockDim.x + threadIdx.x; t < E_EDGES / 4; t += nthr) {
        int4 r = er4[t];
        int base = t * 4;
        int p0 = atomicAdd(&g_cursor[r.x], 1); g_edge_ids[p0] = base + 0;
        int p1 = atomicAdd(&g_cursor[r.y], 1); g_edge_ids[p1] = base + 1;
        int p2 = atomicAdd(&g_cursor[r.z], 1); g_edge_ids[p2] = base + 2;
        int p3 = atomicAdd(&g_cursor[r.w], 1); g_edge_ids[p3] = base + 3;
    }

    // ---- device-wide barrier ----
    __threadfence();
    __syncthreads();
    if (threadIdx.x == 0) {
        atomicAdd(&g_bar, 1);
        while (*(volatile int*)&g_bar < (int)gridDim.x) { __nanosleep(64); }
    }
    __syncthreads();
    __threadfence();

    // ---- phase B: gather segment-sum, warp per node, grid-stride ----
    const int lane   = threadIdx.x & 31;
    const int gw     = (blockIdx.x * blockDim.x + threadIdx.x) >> 5;
    const int nwarps = nthr >> 5;   // 4736
    const float4* ea4 = (const float4*)edge_attr;

    for (int node = gw; node < N_NODES; node += nwarps) {
        int start = g_offset[node];
        int cnt   = g_count[node];
        float4 acc = make_float4(0.f, 0.f, 0.f, 0.f);
        int i = 0;
        for (; i + 8 <= cnt; i += 8) {
            int e[8];
            #pragma unroll
            for (int u = 0; u < 8; u++) e[u] = g_edge_ids[start + i + u];
            float4 v[8];
            #pragma unroll
            for (int u = 0; u < 8; u++) v[u] = ea4[(size_t)e[u] * 32 + lane];
            #pragma unroll
            for (int u = 0; u < 8; u++) {
                acc.x += v[u].x; acc.y += v[u].y; acc.z += v[u].z; acc.w += v[u].w;
            }
        }
        for (; i < cnt; i++) {
            int e = g_edge_ids[start + i];
            float4 v = ea4[(size_t)e * 32 + lane];
            acc.x += v.x; acc.y += v.y; acc.z += v.z; acc.w += v.w;
        }
        ((float4*)g_sum)[(size_t)node * 32 + lane] = acc;
    }
}

// ---------------- 4. MLP via mma.sync (split bf16, interleaved weights) ------
__device__ __forceinline__ void mma_bf16(float4& d,
    uint32_t a0, uint32_t a1, uint32_t a2, uint32_t a3,
    uint32_t b0, uint32_t b1) {
    asm volatile(
        "mma.sync.aligned.m16n8k16.row.col.f32.bf16.bf16.f32 "
        "{%0,%1,%2,%3}, {%4,%5,%6,%7}, {%8,%9}, {%0,%1,%2,%3};"
        : "+f"(d.x), "+f"(d.y), "+f"(d.z), "+f"(d.w)
        : "r"(a0), "r"(a1), "r"(a2), "r"(a3), "r"(b0), "r"(b1));
}
__device__ __forceinline__ void split2(float a, float b, uint32_t& hi, uint32_t& lo) {
    __nv_bfloat16 ha = __float2bfloat16_rn(a);
    __nv_bfloat16 hb = __float2bfloat16_rn(b);
    __nv_bfloat162 H; H.x = ha; H.y = hb;
    hi = *(uint32_t*)&H;
    __nv_bfloat162 L;
    L.x = __float2bfloat16_rn(a - __bfloat162float(ha));
    L.y = __float2bfloat16_rn(b - __bfloat162float(hb));
    lo = *(uint32_t*)&L;
}

#define TILE_M  128
#define N_TILES ((N_NODES + TILE_M - 1) / TILE_M)   // 391
#define W1_BYTES (128 * 68 * 16)   // 139264
#define W2_BYTES (128 * 36 * 16)   // 73728
#define MLP_SMEM (W1_BYTES + W2_BYTES + 256 * 4)   // 214016

__global__ __launch_bounds__(256, 1)
void mlp_mma_kernel(const float* __restrict__ x,
                    const float* __restrict__ W1, const float* __restrict__ b1,
                    const float* __restrict__ W2, const float* __restrict__ b2,
                    float* __restrict__ out) {
    extern __shared__ char smem[];
    char*  W1i = smem;
    char*  W2i = smem + W1_BYTES;
    float* b1s = (float*)(smem + W1_BYTES + W2_BYTES);
    float* b2s = b1s + 128;

    const int tid = threadIdx.x;

    // ---- stage W1/W2 interleaved + split ----
    for (int i = tid; i < 256 * 128; i += 256) {
        int k = i >> 7, j = i & 127;
        float v = W1[i];
        __nv_bfloat16 h = __float2bfloat16_rn(v);
        __nv_bfloat16 l = __float2bfloat16_rn(v - __bfloat162float(h));
        int ks = k >> 4, m = k & 15;
        int q = (m & 7) >> 1, s = m & 1, t = m >> 3;
        char* p8 = W1i + ((j * 68 + ks * 4 + q) << 4) + t * 4 + s * 2;
        *(__nv_bfloat16*)p8 = h;
        *(__nv_bfloat16*)(p8 + 8) = l;
    }
    for (int i = tid; i < 128 * 128; i += 256) {
        int k = i >> 7, j = i & 127;
        float v = W2[i];
        __nv_bfloat16 h = __float2bfloat16_rn(v);
        __nv_bfloat16 l = __float2bfloat16_rn(v - __bfloat162float(h));
        int ks = k >> 4, m = k & 15;
        int q = (m & 7) >> 1, s = m & 1, t = m >> 3;
        char* p8 = W2i + ((j * 36 + ks * 4 + q) << 4) + t * 4 + s * 2;
        *(__nv_bfloat16*)p8 = h;
        *(__nv_bfloat16*)(p8 + 8) = l;
    }
    if (tid < 128) { b1s[tid] = b1[tid]; b2s[tid] = b2[tid]; }
    __syncthreads();

    const int w    = tid >> 5;
    const int lane = tid & 31;
    const int p    = lane >> 2;
    const int q    = lane & 3;
    const char* B1p = W1i + ((p * 68 + q) << 4);
    const char* B2p = W2i + ((p * 36 + q) << 4);

    for (int tile = blockIdx.x; tile < N_TILES; tile += gridDim.x) {
        const int row0 = tile * TILE_M + w * 16 + p;
        const int row1 = row0 + 8;
        const bool ok0 = row0 < N_NODES;
        const bool ok1 = row1 < N_NODES;
        const float* xr0 = x + (size_t)row0 * 128;
        const float* xr1 = x + (size_t)row1 * 128;
        const float* sr0 = g_sum + (size_t)row0 * 128;
        const float* sr1 = g_sum + (size_t)row1 * 128;

        float4 acc[16];
        #pragma unroll
        for (int nf = 0; nf < 16; nf++) acc[nf] = make_float4(0.f, 0.f, 0.f, 0.f);

        // ---- layer 1, software-pipelined A loads ----
        const float2 z = make_float2(0.f, 0.f);
        float2 c00, c01, c10, c11;   // current ks operands
        {
            const int ko = q * 2;
            c00 = ok0 ? *(const float2*)(xr0 + ko)     : z;
            c01 = ok0 ? *(const float2*)(xr0 + ko + 8) : z;
            c10 = ok1 ? *(const float2*)(xr1 + ko)     : z;
            c11 = ok1 ? *(const float2*)(xr1 + ko + 8) : z;
        }
        #pragma unroll
        for (int ks = 0; ks < 16; ks++) {
            // prefetch ks+1
            float2 n00 = z, n01 = z, n10 = z, n11 = z;
            if (ks < 15) {
                const int ksn = ks + 1;
                const float* p0 = (ksn < 8) ? xr0 : sr0;
                const float* p1 = (ksn < 8) ? xr1 : sr1;
                const int ko = (ksn & 7) * 16 + q * 2;
                n00 = ok0 ? *(const float2*)(p0 + ko)     : z;
                n01 = ok0 ? *(const float2*)(p0 + ko + 8) : z;
                n10 = ok1 ? *(const float2*)(p1 + ko)     : z;
                n11 = ok1 ? *(const float2*)(p1 + ko + 8) : z;
            }
            uint32_t a0h, a0l, a1h, a1l, a2h, a2l, a3h, a3l;
            split2(c00.x, c00.y, a0h, a0l);
            split2(c10.x, c10.y, a1h, a1l);
            split2(c01.x, c01.y, a2h, a2l);
            split2(c11.x, c11.y, a3h, a3l);
            const char* wp = B1p + ks * 64;
            #pragma unroll
            for (int nf = 0; nf < 16; nf++) {
                uint4 bw = *(const uint4*)(wp + nf * 8704);   // 8*68*16
                mma_bf16(acc[nf], a0h, a1h, a2h, a3h, bw.x, bw.y);
                mma_bf16(acc[nf], a0h, a1h, a2h, a3h, bw.z, bw.w);
                mma_bf16(acc[nf], a0l, a1l, a2l, a3l, bw.x, bw.y);
            }
            c00 = n00; c01 = n01; c10 = n10; c11 = n11;
        }

        // ---- bias + relu + split -> layer-2 A frags ----
        uint32_t ah[8][4], al[8][4];
        #pragma unroll
        for (int ks2 = 0; ks2 < 8; ks2++) {
            #pragma unroll
            for (int half = 0; half < 2; half++) {
                const int nf = ks2 * 2 + half;
                float2 bv = *(const float2*)&b1s[nf * 8 + q * 2];
                float hx = fmaxf(acc[nf].x + bv.x, 0.f);
                float hy = fmaxf(acc[nf].y + bv.y, 0.f);
                float hz = fmaxf(acc[nf].z + bv.x, 0.f);
                float hw = fmaxf(acc[nf].w + bv.y, 0.f);
                split2(hx, hy, ah[ks2][half * 2 + 0], al[ks2][half * 2 + 0]);
                split2(hz, hw, ah[ks2][half * 2 + 1], al[ks2][half * 2 + 1]);
            }
        }

        // ---- layer 2 ----
        float4 acc2[16];
        #pragma unroll
        for (int nf = 0; nf < 16; nf++) acc2[nf] = make_float4(0.f, 0.f, 0.f, 0.f);

        #pragma unroll
        for (int ks2 = 0; ks2 < 8; ks2++) {
            const char* wp = B2p + ks2 * 64;
            #pragma unroll
            for (int nf = 0; nf < 16; nf++) {
                uint4 bw = *(const uint4*)(wp + nf * 4608);   // 8*36*16
                mma_bf16(acc2[nf], ah[ks2][0], ah[ks2][1], ah[ks2][2], ah[ks2][3], bw.x, bw.y);
                mma_bf16(acc2[nf], ah[ks2][0], ah[ks2][1], ah[ks2][2], ah[ks2][3], bw.z, bw.w);
                mma_bf16(acc2[nf], al[ks2][0], al[ks2][1], al[ks2][2], al[ks2][3], bw.x, bw.y);
            }
        }

        // ---- epilogue: + b2 + residual, store ----
        #pragma unroll
        for (int nf = 0; nf < 16; nf++) {
            const int j = nf * 8 + q * 2;
            float2 bv = *(const float2*)&b2s[j];
            if (ok0) {
                float2 xr = *(const float2*)(xr0 + j);
                float2 o = make_float2(acc2[nf].x + bv.x + xr.x,
                                       acc2[nf].y + bv.y + xr.y);
                *(float2*)(out + (size_t)row0 * 128 + j) = o;
            }
            if (ok1) {
                float2 xr = *(const float2*)(xr1 + j);
                float2 o = make_float2(acc2[nf].z + bv.x + xr.x,
                                       acc2[nf].w + bv.y + xr.y);
                *(float2*)(out + (size_t)row1 * 128 + j) = o;
            }
        }
    }
}

// ---------------- launcher ---------------------------------------------------
extern "C" void kernel_launch(void* const* d_in, const int* in_sizes, int n_in,
                              void* d_out, int out_size) {
    const float* x          = (const float*)d_in[0];
    const int*   edge_row   = (const int*)d_in[1];   // int64 downcast; first E = row
    const float* edge_attr  = (const float*)d_in[2];
    const float* W1         = (const float*)d_in[5];
    const float* b1         = (const float*)d_in[6];
    const float* W2         = (const float*)d_in[7];
    const float* b2         = (const float*)d_in[8];
    float*       out        = (float*)d_out;

    void* gcnt = nullptr;
    cudaGetSymbolAddress(&gcnt, g_count);
    cudaMemsetAsync(gcnt, 0, N_NODES * sizeof(int));
    void* gbar = nullptr;
    cudaGetSymbolAddress(&gbar, g_bar);
    cudaMemsetAsync(gbar, 0, sizeof(int));

    hist4_kernel<<<(E_EDGES / 4 + 255) / 256, 256>>>((const int4*)edge_row);   // kernel 1
    scan_kernel<<<1, 1024>>>();                                                // kernel 2
    fillgather_kernel<<<FG_CTAS, 256>>>((const int4*)edge_row, edge_attr);     // kernel 3
    cudaFuncSetAttribute(mlp_mma_kernel, cudaFuncAttributeMaxDynamicSharedMemorySize, MLP_SMEM);
    mlp_mma_kernel<<<148, 256, MLP_SMEM>>>(x, W1, b1, W2, b2, out);            // kernel 4 (profiled)
}